// round 8
// baseline (speedup 1.0000x reference)
#include <cuda_runtime.h>
#include <cuda_fp16.h>
#include <math_constants.h>

// Problem-shape constants (fixed by setup_inputs)
#define NN   50000
#define EN   400000
#define EEN  800000
#define CN   800000
#define HIDD 128

#define FULLMASK 0xffffffffu

// ---------------- static scratch (no allocation allowed) ----------------
__device__ __half  g_qh[(size_t)EN * HIDD];   // [E,128] q projection (fp16 storage)
__device__ __half  g_kh[(size_t)EN * HIDD];   // [E,128] k projection (fp16 storage)
__device__ float4 g_vsum[EN];                 // [E,4]  per-head summed v
__device__ float2 g_sn[(size_t)EN * 4];       // [E,4] interleaved (exp-sum, exp*vsum)
__device__ float4 g_S3[NN];                   // stage3 per-head exp-sum
__device__ float  g_whk[4];
__device__ float  g_wv[4];
// folded projection weights (computed by k_prep_all, fp32 exact)
__device__ float  g_W2q[32 * 128];            // W2 @ Wq   [32,128]
__device__ float  g_W2k[32 * 128];            // W2 @ Wk   [32,128]
__device__ float  g_bq[128];                  // b2 @ Wq
__device__ float  g_bk[128];                  // b2 @ Wk
__device__ float4 g_W2v[32];                  // W2 @ wvh  [32,4]
__device__ float4 g_bv;                       // b2 @ wvh

// ---------------- f32x2 packed-math helpers (sm_10x) ----------------
__device__ __forceinline__ unsigned long long pk2(float a, float b) {
    unsigned long long r;
    asm("mov.b64 %0, {%1, %2};" : "=l"(r) : "f"(a), "f"(b));
    return r;
}
__device__ __forceinline__ void ffma2(unsigned long long& d,
                                      unsigned long long a,
                                      unsigned long long b) {
    asm("fma.rn.f32x2 %0, %1, %2, %0;" : "+l"(d) : "l"(a), "l"(b));
}
__device__ __forceinline__ float2 unpk(unsigned long long v) {
    float2 r;
    asm("mov.b64 {%0, %1}, %2;" : "=f"(r.x), "=f"(r.y) : "l"(v));
    return r;
}

// ---------------- K_prep_all: all weight folding in one launch ----------------
__global__ void k_prep_all(const float* __restrict__ W2, const float* __restrict__ b2,
                           const float* __restrict__ Wq, const float* __restrict__ Wk,
                           const float* __restrict__ Wv,
                           const float* __restrict__ Wq2,
                           const float* __restrict__ Wk2,
                           const float* __restrict__ Wv2) {
    int idx = blockIdx.x * 256 + threadIdx.x;
    if (idx < 4096) {                       // W2q
        int r = idx >> 7, c = idx & 127;
        float s = 0.f;
        for (int m = 0; m < 128; m++) s += W2[r * 128 + m] * Wq[m * 128 + c];
        g_W2q[idx] = s;
    } else if (idx < 8192) {                // W2k
        int i = idx - 4096;
        int r = i >> 7, c = i & 127;
        float s = 0.f;
        for (int m = 0; m < 128; m++) s += W2[r * 128 + m] * Wk[m * 128 + c];
        g_W2k[i] = s;
    } else if (idx < 8320) {                // bq
        int c = idx - 8192;
        float s = 0.f;
        for (int m = 0; m < 128; m++) s += b2[m] * Wq[m * 128 + c];
        g_bq[c] = s;
    } else if (idx < 8448) {                // bk
        int c = idx - 8320;
        float s = 0.f;
        for (int m = 0; m < 128; m++) s += b2[m] * Wk[m * 128 + c];
        g_bk[c] = s;
    } else if (idx < 8576) {                // W2v [32][4] (wvh recomputed inline)
        int i = idx - 8448;
        int r = i >> 2, hh = i & 3;
        float s = 0.f;
        for (int m = 0; m < 128; m++) {
            float w = 0.f;
            for (int d = 0; d < 32; d++) w += Wv[m * 128 + hh * 32 + d];
            s += W2[r * 128 + m] * w;
        }
        ((float*)&g_W2v[r])[hh] = s;
    } else if (idx < 8580) {                // bv
        int hh = idx - 8576;
        float s = 0.f;
        for (int m = 0; m < 128; m++) {
            float w = 0.f;
            for (int d = 0; d < 32; d++) w += Wv[m * 128 + hh * 32 + d];
            s += b2[m] * w;
        }
        ((float*)&g_bv)[hh] = s;
    } else if (idx < 8584) {                // whk
        int h = idx - 8580;
        float qk = 0.f;
        for (int d = 0; d < 32; d++) qk += Wq2[h * 32 + d] * Wk2[h * 32 + d];
        g_whk[h] = qk * 0.17677669529663687f;   // 1/sqrt(32)
    } else if (idx < 8588) {                // wv
        int h = idx - 8584;
        float vv = 0.f;
        for (int d = 0; d < 32; d++) vv += Wv2[h * 32 + d];
        g_wv[h] = vv;
    }
}

// ---------------- K1: fused edge MLP + folded q/k/vsum projections ----------------
// z = relu(t@W1) (32-wide); q/k/vsum all directly from z via folded weights.
// Warp processes 8 edges per pass; lane t owns output columns 4t..4t+3.
// W2q/W2k interleaved in one SMEM array for a single LDS stream in the hot loop.
#define EPW 8
__global__ void __launch_bounds__(256) k_edge(
    const float* __restrict__ x, const int* __restrict__ ei,
    const float* __restrict__ ea,
    const float* __restrict__ W1, const float* __restrict__ b1,
    float* __restrict__ out, int N, int E)
{
    __shared__ float      W1s[34 * 32];
    __shared__ float      b1s[32];
    __shared__ ulonglong2 Wqk[32 * 64];    // [mb][lane]: even=q pair, odd=k pair interleaved
    __shared__ float4     bqs[32];
    __shared__ float4     bks[32];
    __shared__ float4     W2vs[32];
    __shared__ float4     bvs;

    int tid = threadIdx.x;

    // ---- folded zero-init of accumulators for later kernels ----
    {
        int g = blockIdx.x * 256 + tid;
        const float4 z4 = make_float4(0.f, 0.f, 0.f, 0.f);
        if (g < E) {
            ((float4*)g_sn)[2 * g + 0] = z4;
            ((float4*)g_sn)[2 * g + 1] = z4;
        }
        if (g < N) { g_S3[g] = z4; out[g] = 0.f; }
    }

    for (int i = tid; i < 34 * 32; i += 256) W1s[i] = W1[i];
    if (tid < 32) b1s[tid] = b1[tid];
    for (int i = tid; i < 32 * 32; i += 256) {
        int mb = i >> 5, l = i & 31;
        Wqk[mb * 64 + 2 * l + 0] = ((const ulonglong2*)g_W2q)[i];
        Wqk[mb * 64 + 2 * l + 1] = ((const ulonglong2*)g_W2k)[i];
    }
    if (tid < 32) {
        bqs[tid]  = ((const float4*)g_bq)[tid];
        bks[tid]  = ((const float4*)g_bk)[tid];
        W2vs[tid] = g_W2v[tid];
    }
    if (tid == 0) bvs = g_bv;
    __syncthreads();

    int lane = tid & 31;
    int warp = tid >> 5;
    int gwarp = blockIdx.x * 8 + warp;
    int e0 = gwarp * EPW;
    if (e0 >= E) return;

    float z[EPW];

    // ---- layer 1: z = relu(t @ W1 + b1), t = [xs, xd, ea0..ea31] ----
    #pragma unroll
    for (int j = 0; j < EPW; j++) {
        int e = e0 + j; if (e >= E) e = E - 1;
        int s = ei[e], d = ei[E + e];
        float xs = __ldg(x + s);
        float xd = __ldg(x + d);
        float eav = __ldg(ea + (size_t)e * 32 + lane);

        float acc = b1s[lane];
        acc = fmaf(xs, W1s[lane], acc);
        acc = fmaf(xd, W1s[32 + lane], acc);
        #pragma unroll
        for (int i = 0; i < 32; i++)
            acc = fmaf(__shfl_sync(FULLMASK, eav, i), W1s[(2 + i) * 32 + lane], acc);
        z[j] = fmaxf(acc, 0.f);
    }

    // ---- vsum[e] = z @ W2v + bv  (warp butterfly reduce) ----
    {
        float4 wv = W2vs[lane];
        float4 bv = bvs;
        #pragma unroll
        for (int j = 0; j < EPW; j++) {
            float4 t;
            t.x = z[j] * wv.x; t.y = z[j] * wv.y;
            t.z = z[j] * wv.z; t.w = z[j] * wv.w;
            #pragma unroll
            for (int off = 16; off; off >>= 1) {
                t.x += __shfl_xor_sync(FULLMASK, t.x, off);
                t.y += __shfl_xor_sync(FULLMASK, t.y, off);
                t.z += __shfl_xor_sync(FULLMASK, t.z, off);
                t.w += __shfl_xor_sync(FULLMASK, t.w, off);
            }
            if (lane == 0 && e0 + j < E)
                g_vsum[e0 + j] = make_float4(t.x + bv.x, t.y + bv.y,
                                             t.z + bv.z, t.w + bv.w);
        }
    }

    // ---- q/k projections: K=32, folded weights from SMEM, packed FMA ----
    unsigned long long qa[EPW][2], ka[EPW][2];
    {
        float4 bq = bqs[lane], bk = bks[lane];
        unsigned long long bq01 = pk2(bq.x, bq.y), bq23 = pk2(bq.z, bq.w);
        unsigned long long bk01 = pk2(bk.x, bk.y), bk23 = pk2(bk.z, bk.w);
        #pragma unroll
        for (int j = 0; j < EPW; j++) {
            qa[j][0] = bq01; qa[j][1] = bq23;
            ka[j][0] = bk01; ka[j][1] = bk23;
        }
    }

    #pragma unroll 4
    for (int mb = 0; mb < 32; mb++) {
        ulonglong2 wq = Wqk[mb * 64 + 2 * lane + 0];
        ulonglong2 wk = Wqk[mb * 64 + 2 * lane + 1];
        #pragma unroll
        for (int j = 0; j < EPW; j++) {
            float zb = __shfl_sync(FULLMASK, z[j], mb);
            unsigned long long zd = pk2(zb, zb);
            ffma2(qa[j][0], wq.x, zd);
            ffma2(qa[j][1], wq.y, zd);
            ffma2(ka[j][0], wk.x, zd);
            ffma2(ka[j][1], wk.y, zd);
        }
    }

    // ---- store q/k rounded to fp16 (4 halves = 8B per lane per row) ----
    #pragma unroll
    for (int j = 0; j < EPW; j++) {
        if (e0 + j >= E) break;
        float2 q01 = unpk(qa[j][0]), q23 = unpk(qa[j][1]);
        float2 k01 = unpk(ka[j][0]), k23 = unpk(ka[j][1]);
        __half2 qh0 = __float22half2_rn(q01);
        __half2 qh1 = __float22half2_rn(q23);
        __half2 kh0 = __float22half2_rn(k01);
        __half2 kh1 = __float22half2_rn(k23);
        uint2 qp, kp;
        qp.x = *(unsigned int*)&qh0; qp.y = *(unsigned int*)&qh1;
        kp.x = *(unsigned int*)&kh0; kp.y = *(unsigned int*)&kh1;
        ((uint2*)g_qh)[(size_t)(e0 + j) * 32 + lane] = qp;
        ((uint2*)g_kh)[(size_t)(e0 + j) * 32 + lane] = kp;
    }
}

// ---------------- K2: fused logits + exp + segment accumulation ----------------
// 8 ee-pairs per warp: 16 gathers in flight before any consumption.
// Index reads use streaming hint (__ldcs) so they don't evict q/k from L2.
#define PPW 8
__global__ void __launch_bounds__(256) k_attn(const int* __restrict__ eei, int EE) {
    int warp = (blockIdx.x * 256 + threadIdx.x) >> 5;
    int lane = threadIdx.x & 31;
    int base = warp * PPW;
    if (base >= EE) return;

    int es[PPW], ed[PPW];
    #pragma unroll
    for (int i = 0; i < PPW; i++) {
        int e = base + i; if (e >= EE) e = EE - 1;
        es[i] = __ldcs(eei + e);
        ed[i] = __ldcs(eei + EE + e);
    }

    uint2 qp[PPW], kp[PPW];
    #pragma unroll
    for (int i = 0; i < PPW; i++) {
        qp[i] = __ldg((const uint2*)g_qh + (size_t)ed[i] * 32 + lane);
        kp[i] = __ldg((const uint2*)g_kh + (size_t)es[i] * 32 + lane);
    }

    #pragma unroll
    for (int i = 0; i < PPW; i++) {
        float2 q0 = __half22float2(*(__half2*)&qp[i].x);
        float2 q1 = __half22float2(*(__half2*)&qp[i].y);
        float2 k0 = __half22float2(*(__half2*)&kp[i].x);
        float2 k1 = __half22float2(*(__half2*)&kp[i].y);
        float p = q0.x * k0.x + q0.y * k0.y + q1.x * k1.x + q1.y * k1.y;
        p += __shfl_xor_sync(FULLMASK, p, 1);
        p += __shfl_xor_sync(FULLMASK, p, 2);
        p += __shfl_xor_sync(FULLMASK, p, 4);
        if ((lane & 7) == 0 && base + i < EE) {
            int h = lane >> 3;
            float ex = __expf(p * 0.17677669529663687f);
            float v = ((const float*)g_vsum)[(size_t)es[i] * 4 + h];
            atomicAdd(&g_sn[(size_t)ed[i] * 4 + h], make_float2(ex, ex * v));
        }
    }
}

// ---------------- K_mid: updated_edge_feat + stage3 exp sums (merged) ----------------
__global__ void k_mid(float* __restrict__ out, const float* __restrict__ x,
                      const int* __restrict__ nni, int N, int E, int C) {
    int c = blockIdx.x * blockDim.x + threadIdx.x;
    if (c < E) {
        float4 a = ((const float4*)g_sn)[2 * c + 0];  // (s0,n0,s1,n1)
        float4 b = ((const float4*)g_sn)[2 * c + 1];  // (s2,n2,s3,n3)
        float u = a.y / (a.x + 1e-16f) + a.w / (a.z + 1e-16f)
                + b.y / (b.x + 1e-16f) + b.w / (b.z + 1e-16f);
        out[N + c] = u * (1.f / 128.f);
    }
    if (c < C) {
        int ns = __ldcs(nni + c), nd = __ldcs(nni + C + c);
        float s = __ldg(x + ns) * __ldg(x + nd);
        float4 ev;
        ev.x = __expf(s * g_whk[0]);
        ev.y = __expf(s * g_whk[1]);
        ev.z = __expf(s * g_whk[2]);
        ev.w = __expf(s * g_whk[3]);
        atomicAdd(&g_S3[nd], ev);
    }
}

// ---------------- Stage 3 pass 2: messages -> aggregated node feat ----------------
__global__ void k_n3(float* __restrict__ out, const float* __restrict__ x,
                     const int* __restrict__ nni, int C) {
    int c = blockIdx.x * blockDim.x + threadIdx.x;
    if (c >= C) return;
    int ns = __ldcs(nni + c), nd = __ldcs(nni + C + c);
    float xs = __ldg(x + ns);
    float s = xs * __ldg(x + nd);
    float4 S = g_S3[nd];
    const float* Sf = (const float*)&S;
    float acc = 0.f;
    #pragma unroll
    for (int h = 0; h < 4; h++) {
        float al = __expf(s * g_whk[h]) / (Sf[h] + 1e-16f);
        acc = fmaf(al, g_wv[h], acc);
    }
    atomicAdd(&out[nd], acc * xs * (1.f / 128.f));
}

// ---------------- launch ----------------
extern "C" void kernel_launch(void* const* d_in, const int* in_sizes, int n_in,
                              void* d_out, int out_size) {
    const float* x   = (const float*)d_in[0];
    const int*   ei  = (const int*)d_in[1];
    const float* ea  = (const float*)d_in[2];
    const int*   eei = (const int*)d_in[3];
    const int*   nni = (const int*)d_in[4];
    const float* W1  = (const float*)d_in[5];
    const float* b1  = (const float*)d_in[6];
    const float* W2  = (const float*)d_in[7];
    const float* b2  = (const float*)d_in[8];
    const float* Wq  = (const float*)d_in[9];
    const float* Wk  = (const float*)d_in[10];
    const float* Wv  = (const float*)d_in[11];
    const float* Wq2 = (const float*)d_in[12];
    const float* Wk2 = (const float*)d_in[13];
    const float* Wv2 = (const float*)d_in[14];
    float* out = (float*)d_out;

    int N  = in_sizes[0];
    int E  = in_sizes[1] / 2;
    int EE = in_sizes[3] / 2;
    int C  = in_sizes[4] / 2;

    k_prep_all<<<34, 256>>>(W2, b2, Wq, Wk, Wv, Wq2, Wk2, Wv2);
    k_edge<<<(E + 8 * EPW - 1) / (8 * EPW), 256>>>(x, ei, ea, W1, b1, out, N, E);
    k_attn<<<(EE + 8 * PPW - 1) / (8 * PPW), 256>>>(eei, EE);
    k_mid<<<(C + 255) / 256, 256>>>(out, x, nni, N, E, C);
    k_n3<<<(C + 255) / 256, 256>>>(out, x, nni, C);
}

// round 9
// speedup vs baseline: 1.0949x; 1.0949x over previous
#include <cuda_runtime.h>
#include <cuda_fp16.h>
#include <math_constants.h>

// Problem-shape constants (fixed by setup_inputs)
#define NN   50000
#define EN   400000
#define EEN  800000
#define CN   800000
#define HIDD 128

#define FULLMASK 0xffffffffu

// ---------------- static scratch (no allocation allowed) ----------------
__device__ __half  g_qh[(size_t)EN * HIDD];   // [E,128] q projection (fp16 storage)
__device__ __half  g_kh[(size_t)EN * HIDD];   // [E,128] k projection (fp16 storage)
__device__ float4 g_vsum[EN];                 // [E,4]  per-head summed v
__device__ float2 g_sn[(size_t)EN * 4];       // [E,4] interleaved (exp-sum, exp*vsum)
__device__ float4 g_S3[NN];                   // stage3 per-head exp-sum
__device__ float  g_whk[4];
__device__ float  g_wv[4];
// folded projection weights (computed by k_prep_all, fp32 exact)
__device__ float  g_W2q[32 * 128];            // W2 @ Wq   [32,128]
__device__ float  g_W2k[32 * 128];            // W2 @ Wk   [32,128]
__device__ float  g_bq[128];                  // b2 @ Wq
__device__ float  g_bk[128];                  // b2 @ Wk
__device__ float4 g_W2v[32];                  // W2 @ wvh  [32,4]
__device__ float4 g_bv;                       // b2 @ wvh

// ---------------- f32x2 packed-math helpers (sm_10x) ----------------
__device__ __forceinline__ unsigned long long pk2(float a, float b) {
    unsigned long long r;
    asm("mov.b64 %0, {%1, %2};" : "=l"(r) : "f"(a), "f"(b));
    return r;
}
__device__ __forceinline__ void ffma2(unsigned long long& d,
                                      unsigned long long a,
                                      unsigned long long b) {
    asm("fma.rn.f32x2 %0, %1, %2, %0;" : "+l"(d) : "l"(a), "l"(b));
}
__device__ __forceinline__ float2 unpk(unsigned long long v) {
    float2 r;
    asm("mov.b64 {%0, %1}, %2;" : "=f"(r.x), "=f"(r.y) : "l"(v));
    return r;
}

// ---------------- K_prep_all: weight folding + S3 zero-init ----------------
// grid covers 8704 + N threads. All fp32, exact algebra.
__global__ void k_prep_all(const float* __restrict__ W2, const float* __restrict__ b2,
                           const float* __restrict__ Wq, const float* __restrict__ Wk,
                           const float* __restrict__ Wv,
                           const float* __restrict__ Wq2,
                           const float* __restrict__ Wk2,
                           const float* __restrict__ Wv2, int N) {
    int idx = blockIdx.x * 256 + threadIdx.x;
    if (idx < 4096) {                       // W2q
        int r = idx >> 7, c = idx & 127;
        float s = 0.f;
        for (int m = 0; m < 128; m++) s += W2[r * 128 + m] * Wq[m * 128 + c];
        g_W2q[idx] = s;
    } else if (idx < 8192) {                // W2k
        int i = idx - 4096;
        int r = i >> 7, c = i & 127;
        float s = 0.f;
        for (int m = 0; m < 128; m++) s += W2[r * 128 + m] * Wk[m * 128 + c];
        g_W2k[i] = s;
    } else if (idx < 8320) {                // bq
        int c = idx - 8192;
        float s = 0.f;
        for (int m = 0; m < 128; m++) s += b2[m] * Wq[m * 128 + c];
        g_bq[c] = s;
    } else if (idx < 8448) {                // bk
        int c = idx - 8320;
        float s = 0.f;
        for (int m = 0; m < 128; m++) s += b2[m] * Wk[m * 128 + c];
        g_bk[c] = s;
    } else if (idx < 8576) {                // W2v [32][4] (wvh recomputed inline)
        int i = idx - 8448;
        int r = i >> 2, hh = i & 3;
        float s = 0.f;
        for (int m = 0; m < 128; m++) {
            float w = 0.f;
            for (int d = 0; d < 32; d++) w += Wv[m * 128 + hh * 32 + d];
            s += W2[r * 128 + m] * w;
        }
        ((float*)&g_W2v[r])[hh] = s;
    } else if (idx < 8580) {                // bv
        int hh = idx - 8576;
        float s = 0.f;
        for (int m = 0; m < 128; m++) {
            float w = 0.f;
            for (int d = 0; d < 32; d++) w += Wv[m * 128 + hh * 32 + d];
            s += b2[m] * w;
        }
        ((float*)&g_bv)[hh] = s;
    } else if (idx < 8584) {                // whk
        int h = idx - 8580;
        float qk = 0.f;
        for (int d = 0; d < 32; d++) qk += Wq2[h * 32 + d] * Wk2[h * 32 + d];
        g_whk[h] = qk * 0.17677669529663687f;   // 1/sqrt(32)
    } else if (idx < 8588) {                // wv
        int h = idx - 8584;
        float vv = 0.f;
        for (int d = 0; d < 32; d++) vv += Wv2[h * 32 + d];
        g_wv[h] = vv;
    } else {                                // zero g_S3 (consumed by k_edge atomics)
        int j = idx - 8704;
        if (j >= 0 && j < N)
            g_S3[j] = make_float4(0.f, 0.f, 0.f, 0.f);
    }
}

// ---------------- K1: fused edge MLP + folded q/k/vsum projections ----------------
// z = relu(t@W1) (32-wide); q/k/vsum all directly from z via folded weights.
// Warp processes 8 edges per pass; lane t owns output columns 4t..4t+3.
// Prologue additionally: zeroes g_sn/out, AND performs the whole stage-3
// exp-sum accumulation (independent of this kernel's outputs) — that memory
// work rides free under the FMA-bound main body.
#define EPW 8
__global__ void __launch_bounds__(256) k_edge(
    const float* __restrict__ x, const int* __restrict__ ei,
    const float* __restrict__ ea,
    const float* __restrict__ W1, const float* __restrict__ b1,
    const int* __restrict__ nni,
    float* __restrict__ out, int N, int E, int C)
{
    __shared__ float      W1s[34 * 32];
    __shared__ float      b1s[32];
    __shared__ ulonglong2 W2qs[32 * 32];   // [k][lane] -> cols 4l..4l+3 packed
    __shared__ ulonglong2 W2ks[32 * 32];
    __shared__ float4     bqs[32];
    __shared__ float4     bks[32];
    __shared__ float4     W2vs[32];
    __shared__ float4     bvs;

    int tid = threadIdx.x;

    // ---- folded zero-init + stage-3 S3 accumulation ----
    {
        int g = blockIdx.x * 256 + tid;
        const float4 z4 = make_float4(0.f, 0.f, 0.f, 0.f);
        if (g < E) {
            ((float4*)g_sn)[2 * g + 0] = z4;
            ((float4*)g_sn)[2 * g + 1] = z4;
        }
        if (g < N) out[g] = 0.f;
        if (g < C) {
            int ns = nni[g], nd = nni[C + g];
            float s = __ldg(x + ns) * __ldg(x + nd);
            float4 ev;
            ev.x = __expf(s * g_whk[0]);
            ev.y = __expf(s * g_whk[1]);
            ev.z = __expf(s * g_whk[2]);
            ev.w = __expf(s * g_whk[3]);
            atomicAdd(&g_S3[nd], ev);
        }
    }

    for (int i = tid; i < 34 * 32; i += 256) W1s[i] = W1[i];
    if (tid < 32) b1s[tid] = b1[tid];
    for (int i = tid; i < 32 * 32; i += 256) {
        W2qs[i] = ((const ulonglong2*)g_W2q)[i];
        W2ks[i] = ((const ulonglong2*)g_W2k)[i];
    }
    if (tid < 32) {
        bqs[tid]  = ((const float4*)g_bq)[tid];
        bks[tid]  = ((const float4*)g_bk)[tid];
        W2vs[tid] = g_W2v[tid];
    }
    if (tid == 0) bvs = g_bv;
    __syncthreads();

    int lane = tid & 31;
    int warp = tid >> 5;
    int gwarp = blockIdx.x * 8 + warp;
    int e0 = gwarp * EPW;
    if (e0 >= E) return;

    float z[EPW];

    // ---- layer 1: z = relu(t @ W1 + b1), t = [xs, xd, ea0..ea31] ----
    #pragma unroll
    for (int j = 0; j < EPW; j++) {
        int e = e0 + j; if (e >= E) e = E - 1;
        int s = ei[e], d = ei[E + e];
        float xs = __ldg(x + s);
        float xd = __ldg(x + d);
        float eav = __ldg(ea + (size_t)e * 32 + lane);

        float acc = b1s[lane];
        acc = fmaf(xs, W1s[lane], acc);
        acc = fmaf(xd, W1s[32 + lane], acc);
        #pragma unroll
        for (int i = 0; i < 32; i++)
            acc = fmaf(__shfl_sync(FULLMASK, eav, i), W1s[(2 + i) * 32 + lane], acc);
        z[j] = fmaxf(acc, 0.f);
    }

    // ---- vsum[e] = z @ W2v + bv  (warp butterfly reduce) ----
    {
        float4 wv = W2vs[lane];
        float4 bv = bvs;
        #pragma unroll
        for (int j = 0; j < EPW; j++) {
            float4 t;
            t.x = z[j] * wv.x; t.y = z[j] * wv.y;
            t.z = z[j] * wv.z; t.w = z[j] * wv.w;
            #pragma unroll
            for (int off = 16; off; off >>= 1) {
                t.x += __shfl_xor_sync(FULLMASK, t.x, off);
                t.y += __shfl_xor_sync(FULLMASK, t.y, off);
                t.z += __shfl_xor_sync(FULLMASK, t.z, off);
                t.w += __shfl_xor_sync(FULLMASK, t.w, off);
            }
            if (lane == 0 && e0 + j < E)
                g_vsum[e0 + j] = make_float4(t.x + bv.x, t.y + bv.y,
                                             t.z + bv.z, t.w + bv.w);
        }
    }

    // ---- q/k projections: K=32, folded weights from SMEM, packed FMA ----
    unsigned long long qa[EPW][2], ka[EPW][2];
    {
        float4 bq = bqs[lane], bk = bks[lane];
        unsigned long long bq01 = pk2(bq.x, bq.y), bq23 = pk2(bq.z, bq.w);
        unsigned long long bk01 = pk2(bk.x, bk.y), bk23 = pk2(bk.z, bk.w);
        #pragma unroll
        for (int j = 0; j < EPW; j++) {
            qa[j][0] = bq01; qa[j][1] = bq23;
            ka[j][0] = bk01; ka[j][1] = bk23;
        }
    }

    #pragma unroll 4
    for (int mb = 0; mb < 32; mb++) {
        ulonglong2 wq = W2qs[mb * 32 + lane];
        ulonglong2 wk = W2ks[mb * 32 + lane];
        #pragma unroll
        for (int j = 0; j < EPW; j++) {
            float zb = __shfl_sync(FULLMASK, z[j], mb);
            unsigned long long zd = pk2(zb, zb);
            ffma2(qa[j][0], wq.x, zd);
            ffma2(qa[j][1], wq.y, zd);
            ffma2(ka[j][0], wk.x, zd);
            ffma2(ka[j][1], wk.y, zd);
        }
    }

    // ---- store q/k rounded to fp16 (4 halves = 8B per lane per row) ----
    #pragma unroll
    for (int j = 0; j < EPW; j++) {
        if (e0 + j >= E) break;
        float2 q01 = unpk(qa[j][0]), q23 = unpk(qa[j][1]);
        float2 k01 = unpk(ka[j][0]), k23 = unpk(ka[j][1]);
        __half2 qh0 = __float22half2_rn(q01);
        __half2 qh1 = __float22half2_rn(q23);
        __half2 kh0 = __float22half2_rn(k01);
        __half2 kh1 = __float22half2_rn(k23);
        uint2 qp, kp;
        qp.x = *(unsigned int*)&qh0; qp.y = *(unsigned int*)&qh1;
        kp.x = *(unsigned int*)&kh0; kp.y = *(unsigned int*)&kh1;
        ((uint2*)g_qh)[(size_t)(e0 + j) * 32 + lane] = qp;
        ((uint2*)g_kh)[(size_t)(e0 + j) * 32 + lane] = kp;
    }
}

// ---------------- K2: fused logits + exp + segment accumulation ----------------
// 4 ee-pairs per warp (R6 config: low regs, at random-gather DRAM floor).
// fp16 q/k, fp32 dot. Vector float2 atomics merge (exp-sum, exp*v).
#define PPW 4
__global__ void __launch_bounds__(256) k_attn(const int* __restrict__ eei, int EE) {
    int warp = (blockIdx.x * 256 + threadIdx.x) >> 5;
    int lane = threadIdx.x & 31;
    int base = warp * PPW;
    if (base >= EE) return;

    int es[PPW], ed[PPW];
    #pragma unroll
    for (int i = 0; i < PPW; i++) {
        int e = base + i; if (e >= EE) e = EE - 1;
        es[i] = __ldg(eei + e);
        ed[i] = __ldg(eei + EE + e);
    }

    uint2 qp[PPW], kp[PPW];
    #pragma unroll
    for (int i = 0; i < PPW; i++) {
        qp[i] = __ldg((const uint2*)g_qh + (size_t)ed[i] * 32 + lane);
        kp[i] = __ldg((const uint2*)g_kh + (size_t)es[i] * 32 + lane);
    }

    #pragma unroll
    for (int i = 0; i < PPW; i++) {
        float2 q0 = __half22float2(*(__half2*)&qp[i].x);
        float2 q1 = __half22float2(*(__half2*)&qp[i].y);
        float2 k0 = __half22float2(*(__half2*)&kp[i].x);
        float2 k1 = __half22float2(*(__half2*)&kp[i].y);
        float p = q0.x * k0.x + q0.y * k0.y + q1.x * k1.x + q1.y * k1.y;
        p += __shfl_xor_sync(FULLMASK, p, 1);
        p += __shfl_xor_sync(FULLMASK, p, 2);
        p += __shfl_xor_sync(FULLMASK, p, 4);
        if ((lane & 7) == 0 && base + i < EE) {
            int h = lane >> 3;
            float ex = __expf(p * 0.17677669529663687f);
            float v = ((const float*)g_vsum)[(size_t)es[i] * 4 + h];
            atomicAdd(&g_sn[(size_t)ed[i] * 4 + h], make_float2(ex, ex * v));
        }
    }
}

// ---------------- K3: uef + stage3 messages (merged final pass) ----------------
__global__ void k_n3(float* __restrict__ out, const float* __restrict__ x,
                     const int* __restrict__ nni, int N, int E, int C) {
    int c = blockIdx.x * blockDim.x + threadIdx.x;
    if (c < E) {
        float4 a = ((const float4*)g_sn)[2 * c + 0];  // (s0,n0,s1,n1)
        float4 b = ((const float4*)g_sn)[2 * c + 1];  // (s2,n2,s3,n3)
        float u = a.y / (a.x + 1e-16f) + a.w / (a.z + 1e-16f)
                + b.y / (b.x + 1e-16f) + b.w / (b.z + 1e-16f);
        out[N + c] = u * (1.f / 128.f);
    }
    if (c < C) {
        int ns = nni[c], nd = nni[C + c];
        float xs = __ldg(x + ns);
        float s = xs * __ldg(x + nd);
        float4 S = g_S3[nd];
        const float* Sf = (const float*)&S;
        float acc = 0.f;
        #pragma unroll
        for (int h = 0; h < 4; h++) {
            float al = __expf(s * g_whk[h]) / (Sf[h] + 1e-16f);
            acc = fmaf(al, g_wv[h], acc);
        }
        atomicAdd(&out[nd], acc * xs * (1.f / 128.f));
    }
}

// ---------------- launch ----------------
extern "C" void kernel_launch(void* const* d_in, const int* in_sizes, int n_in,
                              void* d_out, int out_size) {
    const float* x   = (const float*)d_in[0];
    const int*   ei  = (const int*)d_in[1];
    const float* ea  = (const float*)d_in[2];
    const int*   eei = (const int*)d_in[3];
    const int*   nni = (const int*)d_in[4];
    const float* W1  = (const float*)d_in[5];
    const float* b1  = (const float*)d_in[6];
    const float* W2  = (const float*)d_in[7];
    const float* b2  = (const float*)d_in[8];
    const float* Wq  = (const float*)d_in[9];
    const float* Wk  = (const float*)d_in[10];
    const float* Wv  = (const float*)d_in[11];
    const float* Wq2 = (const float*)d_in[12];
    const float* Wk2 = (const float*)d_in[13];
    const float* Wv2 = (const float*)d_in[14];
    float* out = (float*)d_out;

    int N  = in_sizes[0];
    int E  = in_sizes[1] / 2;
    int EE = in_sizes[3] / 2;
    int C  = in_sizes[4] / 2;

    k_prep_all<<<(8704 + N + 255) / 256, 256>>>(W2, b2, Wq, Wk, Wv, Wq2, Wk2, Wv2, N);
    k_edge<<<(E + 8 * EPW - 1) / (8 * EPW), 256>>>(x, ei, ea, W1, b1, nni, out, N, E, C);
    k_attn<<<(EE + 8 * PPW - 1) / (8 * PPW), 256>>>(eei, EE);
    k_n3<<<(C + 255) / 256, 256>>>(out, x, nni, N, E, C);
}